// round 5
// baseline (speedup 1.0000x reference)
#include <cuda_runtime.h>
#include <cstdint>

// Problem constants (GCNN3L: N=100000 nodes, F=64 features, 8 outputs)
#define NN 100000
#define EE 1600000
#define F  64
#define OUTF 8

// Scratch (static device globals -- no allocation allowed)
__device__ __align__(256) float g_tmp[(size_t)NN * F];   // GEMM output (pre-norm messages)
__device__ __align__(256) float g_agg[(size_t)NN * F];   // aggregation buffer (next layer input)
__device__ __align__(256) float g_dis[NN];               // deg -> rsqrt(deg)
__device__ __align__(256) float g_norm[EE];              // per-edge dis[src]*dis[dst]

// ---------------------------------------------------------------------------
// Degree / normalization   (edge_index arrives as int32: [2, E] row-major)
// ---------------------------------------------------------------------------
__global__ void k_dis_init(int n) {
    int i = blockIdx.x * blockDim.x + threadIdx.x;
    if (i < n) g_dis[i] = 1.0f;  // self-loop contributes 1 to degree
}

__global__ void k_deg_acc(const int* __restrict__ ei, int E) {
    int e = blockIdx.x * blockDim.x + threadIdx.x;
    if (e < E) {
        int dst = ei[E + e];
        atomicAdd(&g_dis[dst], 1.0f);
    }
}

__global__ void k_rsqrt(int n) {
    int i = blockIdx.x * blockDim.x + threadIdx.x;
    if (i < n) g_dis[i] = rsqrtf(g_dis[i]);
}

// Precompute per-edge normalization (runs once; reused by 3 scatters)
__global__ void k_edge_norm(const int* __restrict__ ei, int E) {
    int e = blockIdx.x * blockDim.x + threadIdx.x;
    if (e < E) g_norm[e] = g_dis[ei[e]] * g_dis[ei[E + e]];
}

// ---------------------------------------------------------------------------
// GEMM: tmp = (relu?)(hin) @ W   [N,64]x[64,64]
// Also initializes agg = b + tmp * dis^2  (bias + self-loop message)
// If use_agg_in != 0, input is g_agg (previous layer output) with ReLU.
// ---------------------------------------------------------------------------
#define GEMM_ROWS 4
__global__ void k_gemm(const float* __restrict__ hin_ext,
                       const float* __restrict__ W,
                       const float* __restrict__ b,
                       int n, int use_agg_in) {
    __shared__ float Ws[F * F];
    __shared__ float hs[GEMM_ROWS][F];

    int tx  = threadIdx.x;           // 0..63  (output feature)
    int ty  = threadIdx.y;           // 0..GEMM_ROWS-1 (row within block)
    int tid = ty * F + tx;

    for (int i = tid; i < F * F; i += F * GEMM_ROWS) Ws[i] = W[i];

    int row = blockIdx.x * GEMM_ROWS + ty;
    if (row < n) {
        float v;
        if (use_agg_in) {
            v = fmaxf(g_agg[(size_t)row * F + tx], 0.0f);  // fused ReLU
        } else {
            v = hin_ext[(size_t)row * F + tx];
        }
        hs[ty][tx] = v;
    }
    __syncthreads();

    if (row < n) {
        float acc = 0.0f;
#pragma unroll
        for (int k = 0; k < F; k++)
            acc = fmaf(hs[ty][k], Ws[k * F + tx], acc);

        g_tmp[(size_t)row * F + tx] = acc;
        float d = g_dis[row];
        // self-loop message norm = dis[i]*dis[i]; fold bias in too
        g_agg[(size_t)row * F + tx] = b[tx] + acc * d * d;
    }
}

// ---------------------------------------------------------------------------
// Scatter: for each edge, agg[dst] += tmp[src] * norm[e]
// 16 threads per edge, one float4 gather per thread, 4 scalar REDs.
// ---------------------------------------------------------------------------
__global__ void k_scatter(const int* __restrict__ ei, int E) {
    long long t = (long long)blockIdx.x * blockDim.x + threadIdx.x;
    int e  = (int)(t >> 4);          // edge index
    int f4 = (int)(t & 15);          // which float4 of the 64-float row
    if (e >= E) return;

    int   src  = ei[e];              // broadcast within 16-thread group (L1 hit)
    int   dst  = ei[E + e];
    float norm = g_norm[e];

    const float4 v = *reinterpret_cast<const float4*>(g_tmp + (size_t)src * F + f4 * 4);

    float* p = g_agg + (size_t)dst * F + f4 * 4;
    atomicAdd(p + 0, v.x * norm);
    atomicAdd(p + 1, v.y * norm);
    atomicAdd(p + 2, v.z * norm);
    atomicAdd(p + 3, v.w * norm);
}

// ---------------------------------------------------------------------------
// Final linear: out = relu(agg) @ Wl + bl   [N,64]x[64,8]
// ---------------------------------------------------------------------------
__global__ void k_final(const float* __restrict__ Wl,
                        const float* __restrict__ bl,
                        float* __restrict__ out, int n) {
    __shared__ float Wls[F * OUTF];
    __shared__ float hs[32][F + 1];

    int tx  = threadIdx.x;  // 0..7
    int ty  = threadIdx.y;  // 0..31
    int tid = ty * OUTF + tx;

    for (int i = tid; i < F * OUTF; i += 256) Wls[i] = Wl[i];

    int row0 = blockIdx.x * 32;
    for (int i = tid; i < 32 * F; i += 256) {
        int r = row0 + i / F;
        hs[i / F][i % F] = (r < n) ? fmaxf(g_agg[(size_t)r * F + (i % F)], 0.0f) : 0.0f;
    }
    __syncthreads();

    int row = row0 + ty;
    if (row < n) {
        float acc = bl[tx];
#pragma unroll
        for (int k = 0; k < F; k++)
            acc = fmaf(hs[ty][k], Wls[k * OUTF + tx], acc);
        out[(size_t)row * OUTF + tx] = acc;
    }
}

// ---------------------------------------------------------------------------
// Launch
// ---------------------------------------------------------------------------
extern "C" void kernel_launch(void* const* d_in, const int* in_sizes, int n_in,
                              void* d_out, int out_size) {
    const float* x  = (const float*)d_in[0];
    const int*   ei = (const int*)d_in[1];     // int32 edge_index (JAX x64 disabled)
    const float* W1 = (const float*)d_in[2];
    const float* b1 = (const float*)d_in[3];
    const float* W2 = (const float*)d_in[4];
    const float* b2 = (const float*)d_in[5];
    const float* W3 = (const float*)d_in[6];
    const float* b3 = (const float*)d_in[7];
    const float* Wl = (const float*)d_in[8];
    const float* bl = (const float*)d_in[9];
    float* out = (float*)d_out;

    int n = in_sizes[0] / F;        // 100000
    int E = in_sizes[1] / 2;        // 1600000

    unsigned egrid = (unsigned)((E + 255) / 256);

    // --- normalization + edge preprocessing ---
    k_dis_init<<<(n + 255) / 256, 256>>>(n);
    k_deg_acc<<<egrid, 256>>>(ei, E);
    k_rsqrt<<<(n + 255) / 256, 256>>>(n);
    k_edge_norm<<<egrid, 256>>>(ei, E);

    dim3 gemm_block(F, GEMM_ROWS);
    unsigned gemm_grid = (n + GEMM_ROWS - 1) / GEMM_ROWS;
    unsigned scat_grid = (unsigned)(((long long)E * 16 + 255) / 256);

    // --- layer 1 ---
    k_gemm<<<gemm_grid, gemm_block>>>(x, W1, b1, n, 0);
    k_scatter<<<scat_grid, 256>>>(ei, E);
    // --- layer 2 (relu fused into gemm read) ---
    k_gemm<<<gemm_grid, gemm_block>>>(nullptr, W2, b2, n, 1);
    k_scatter<<<scat_grid, 256>>>(ei, E);
    // --- layer 3 ---
    k_gemm<<<gemm_grid, gemm_block>>>(nullptr, W3, b3, n, 1);
    k_scatter<<<scat_grid, 256>>>(ei, E);

    // --- final linear (relu fused) ---
    dim3 fin_block(OUTF, 32);
    k_final<<<(n + 31) / 32, fin_block>>>(Wl, bl, out, n);
}

// round 6
// speedup vs baseline: 1.2365x; 1.2365x over previous
#include <cuda_runtime.h>
#include <cstdint>

// Problem constants (GCNN3L: N=100000 nodes, F=64 features, 8 outputs)
#define NN 100000
#define EE 1600000
#define F  64
#define OUTF 8

#define SCAN_B 256
#define NB1 ((NN + SCAN_B - 1) / SCAN_B)   // 391

// Scratch (static device globals -- no allocation allowed)
__device__ __align__(256) float g_tmp[(size_t)NN * F];   // GEMM output (pre-norm messages)
__device__ __align__(256) float g_agg[(size_t)NN * F];   // aggregation buffer (next layer input)
__device__ __align__(256) float g_dis[NN];               // rsqrt(deg)
__device__ __align__(256) int   g_cnt[NN];               // in-degree (excl. self loop)
__device__ __align__(256) int   g_fill[NN];              // placement cursor
__device__ __align__(256) int   g_rowstart[NN];          // CSR row offsets (exclusive scan)
__device__ __align__(256) int   g_bsum[512];             // scan block sums
__device__ __align__(256) int   g_boff[512];             // scan block offsets
__device__ __align__(256) int2  g_epack[EE];             // per-edge (src, norm-bits), dst-sorted

// ---------------------------------------------------------------------------
// CSR build: count, dis, scan, place
// ---------------------------------------------------------------------------
__global__ void k_zero(int n) {
    int i = blockIdx.x * blockDim.x + threadIdx.x;
    if (i < n) { g_cnt[i] = 0; g_fill[i] = 0; }
}

__global__ void k_count(const int* __restrict__ ei, int E) {
    int e = blockIdx.x * blockDim.x + threadIdx.x;
    if (e < E) atomicAdd(&g_cnt[ei[E + e]], 1);
}

__global__ void k_dis(int n) {
    int i = blockIdx.x * blockDim.x + threadIdx.x;
    if (i < n) g_dis[i] = rsqrtf((float)(g_cnt[i] + 1));  // +1 self loop
}

__global__ void k_scan1(int n) {
    __shared__ int s[SCAN_B];
    int i = blockIdx.x * SCAN_B + threadIdx.x;
    int v = (i < n) ? g_cnt[i] : 0;
    s[threadIdx.x] = v;
    __syncthreads();
    for (int off = 1; off < SCAN_B; off <<= 1) {
        int t = (threadIdx.x >= off) ? s[threadIdx.x - off] : 0;
        __syncthreads();
        s[threadIdx.x] += t;
        __syncthreads();
    }
    if (i < n) g_rowstart[i] = s[threadIdx.x] - v;         // exclusive within block
    if (threadIdx.x == SCAN_B - 1) g_bsum[blockIdx.x] = s[SCAN_B - 1];
}

__global__ void k_scan2(int nb) {   // single block, 512 threads
    __shared__ int s[512];
    int v = (threadIdx.x < nb) ? g_bsum[threadIdx.x] : 0;
    s[threadIdx.x] = v;
    __syncthreads();
    for (int off = 1; off < 512; off <<= 1) {
        int t = (threadIdx.x >= off) ? s[threadIdx.x - off] : 0;
        __syncthreads();
        s[threadIdx.x] += t;
        __syncthreads();
    }
    if (threadIdx.x < nb) g_boff[threadIdx.x] = s[threadIdx.x] - v;  // exclusive
}

__global__ void k_scan3(int n) {
    int i = blockIdx.x * SCAN_B + threadIdx.x;
    if (i < n) g_rowstart[i] += g_boff[blockIdx.x];
}

__global__ void k_place(const int* __restrict__ ei, int E) {
    int e = blockIdx.x * blockDim.x + threadIdx.x;
    if (e < E) {
        int src = ei[e];
        int dst = ei[E + e];
        int pos = g_rowstart[dst] + atomicAdd(&g_fill[dst], 1);
        float norm = g_dis[src] * g_dis[dst];
        g_epack[pos] = make_int2(src, __float_as_int(norm));
    }
}

// ---------------------------------------------------------------------------
// GEMM: tmp = (relu?)(hin) @ W   [N,64]x[64,64]
// Also initializes agg = b + tmp * dis^2  (bias + self-loop message)
// ---------------------------------------------------------------------------
#define GEMM_ROWS 4
__global__ void k_gemm(const float* __restrict__ hin_ext,
                       const float* __restrict__ W,
                       const float* __restrict__ b,
                       int n, int use_agg_in) {
    __shared__ float Ws[F * F];
    __shared__ float hs[GEMM_ROWS][F];

    int tx  = threadIdx.x;           // 0..63  (output feature)
    int ty  = threadIdx.y;           // 0..GEMM_ROWS-1
    int tid = ty * F + tx;

    for (int i = tid; i < F * F; i += F * GEMM_ROWS) Ws[i] = W[i];

    int row = blockIdx.x * GEMM_ROWS + ty;
    if (row < n) {
        float v;
        if (use_agg_in) {
            v = fmaxf(g_agg[(size_t)row * F + tx], 0.0f);  // fused ReLU
        } else {
            v = hin_ext[(size_t)row * F + tx];
        }
        hs[ty][tx] = v;
    }
    __syncthreads();

    if (row < n) {
        float acc = 0.0f;
#pragma unroll
        for (int k = 0; k < F; k++)
            acc = fmaf(hs[ty][k], Ws[k * F + tx], acc);

        g_tmp[(size_t)row * F + tx] = acc;
        float d = g_dis[row];
        g_agg[(size_t)row * F + tx] = b[tx] + acc * d * d;  // bias + self-loop
    }
}

// ---------------------------------------------------------------------------
// Aggregation (CSR gather, NO atomics): for each node i,
//   agg[i] += sum_{e in row(i)} tmp[src(e)] * norm(e)
// 16 threads per node, each owns one float4 slice; 2-way unrolled MLP.
// ---------------------------------------------------------------------------
__global__ void k_agg(int n) {
    int tx   = threadIdx.x & 15;         // float4 slice 0..15
    int g    = threadIdx.x >> 4;         // node group within block 0..15
    int node = blockIdx.x * 16 + g;
    if (node >= n) return;

    int start = g_rowstart[node];
    int end   = start + g_cnt[node];

    float4 a0 = make_float4(0.f, 0.f, 0.f, 0.f);
    float4 a1 = make_float4(0.f, 0.f, 0.f, 0.f);

    int k = start;
    for (; k + 1 < end; k += 2) {
        int2 p0 = g_epack[k];
        int2 p1 = g_epack[k + 1];
        float n0 = __int_as_float(p0.y);
        float n1 = __int_as_float(p1.y);
        const float4 v0 = *reinterpret_cast<const float4*>(g_tmp + (size_t)p0.x * F + tx * 4);
        const float4 v1 = *reinterpret_cast<const float4*>(g_tmp + (size_t)p1.x * F + tx * 4);
        a0.x = fmaf(v0.x, n0, a0.x); a0.y = fmaf(v0.y, n0, a0.y);
        a0.z = fmaf(v0.z, n0, a0.z); a0.w = fmaf(v0.w, n0, a0.w);
        a1.x = fmaf(v1.x, n1, a1.x); a1.y = fmaf(v1.y, n1, a1.y);
        a1.z = fmaf(v1.z, n1, a1.z); a1.w = fmaf(v1.w, n1, a1.w);
    }
    if (k < end) {
        int2 p0 = g_epack[k];
        float n0 = __int_as_float(p0.y);
        const float4 v0 = *reinterpret_cast<const float4*>(g_tmp + (size_t)p0.x * F + tx * 4);
        a0.x = fmaf(v0.x, n0, a0.x); a0.y = fmaf(v0.y, n0, a0.y);
        a0.z = fmaf(v0.z, n0, a0.z); a0.w = fmaf(v0.w, n0, a0.w);
    }

    float* pa = g_agg + (size_t)node * F + tx * 4;
    float4 cur = *reinterpret_cast<float4*>(pa);
    cur.x += a0.x + a1.x;
    cur.y += a0.y + a1.y;
    cur.z += a0.z + a1.z;
    cur.w += a0.w + a1.w;
    *reinterpret_cast<float4*>(pa) = cur;
}

// ---------------------------------------------------------------------------
// Final linear: out = relu(agg) @ Wl + bl   [N,64]x[64,8]
// ---------------------------------------------------------------------------
__global__ void k_final(const float* __restrict__ Wl,
                        const float* __restrict__ bl,
                        float* __restrict__ out, int n) {
    __shared__ float Wls[F * OUTF];
    __shared__ float hs[32][F + 1];

    int tx  = threadIdx.x;  // 0..7
    int ty  = threadIdx.y;  // 0..31
    int tid = ty * OUTF + tx;

    for (int i = tid; i < F * OUTF; i += 256) Wls[i] = Wl[i];

    int row0 = blockIdx.x * 32;
    for (int i = tid; i < 32 * F; i += 256) {
        int r = row0 + i / F;
        hs[i / F][i % F] = (r < n) ? fmaxf(g_agg[(size_t)r * F + (i % F)], 0.0f) : 0.0f;
    }
    __syncthreads();

    int row = row0 + ty;
    if (row < n) {
        float acc = bl[tx];
#pragma unroll
        for (int k = 0; k < F; k++)
            acc = fmaf(hs[ty][k], Wls[k * OUTF + tx], acc);
        out[(size_t)row * OUTF + tx] = acc;
    }
}

// ---------------------------------------------------------------------------
// Launch
// ---------------------------------------------------------------------------
extern "C" void kernel_launch(void* const* d_in, const int* in_sizes, int n_in,
                              void* d_out, int out_size) {
    const float* x  = (const float*)d_in[0];
    const int*   ei = (const int*)d_in[1];     // int32 edge_index [2, E]
    const float* W1 = (const float*)d_in[2];
    const float* b1 = (const float*)d_in[3];
    const float* W2 = (const float*)d_in[4];
    const float* b2 = (const float*)d_in[5];
    const float* W3 = (const float*)d_in[6];
    const float* b3 = (const float*)d_in[7];
    const float* Wl = (const float*)d_in[8];
    const float* bl = (const float*)d_in[9];
    float* out = (float*)d_out;

    int n = in_sizes[0] / F;        // 100000
    int E = in_sizes[1] / 2;        // 1600000

    unsigned ngrid = (unsigned)((n + 255) / 256);
    unsigned egrid = (unsigned)((E + 255) / 256);
    unsigned sgrid = (unsigned)((n + SCAN_B - 1) / SCAN_B);

    // --- CSR build (once per call, reused by 3 aggregations) ---
    k_zero<<<ngrid, 256>>>(n);
    k_count<<<egrid, 256>>>(ei, E);
    k_dis<<<ngrid, 256>>>(n);
    k_scan1<<<sgrid, SCAN_B>>>(n);
    k_scan2<<<1, 512>>>((int)sgrid);
    k_scan3<<<sgrid, SCAN_B>>>(n);
    k_place<<<egrid, 256>>>(ei, E);

    dim3 gemm_block(F, GEMM_ROWS);
    unsigned gemm_grid = (n + GEMM_ROWS - 1) / GEMM_ROWS;
    unsigned agg_grid  = (unsigned)((n + 15) / 16);

    // --- layer 1 ---
    k_gemm<<<gemm_grid, gemm_block>>>(x, W1, b1, n, 0);
    k_agg<<<agg_grid, 256>>>(n);
    // --- layer 2 (relu fused into gemm read) ---
    k_gemm<<<gemm_grid, gemm_block>>>(nullptr, W2, b2, n, 1);
    k_agg<<<agg_grid, 256>>>(n);
    // --- layer 3 ---
    k_gemm<<<gemm_grid, gemm_block>>>(nullptr, W3, b3, n, 1);
    k_agg<<<agg_grid, 256>>>(n);

    // --- final linear (relu fused) ---
    dim3 fin_block(OUTF, 32);
    k_final<<<(n + 31) / 32, fin_block>>>(Wl, bl, out, n);
}

// round 7
// speedup vs baseline: 3.2456x; 2.6247x over previous
#include <cuda_runtime.h>
#include <cstdint>

// Problem constants (GCNN3L: N=100000 nodes, F=64 features, 8 outputs)
#define NN 100000
#define EE 1600000
#define F  64
#define OUTF 8

#define SCAN_B 256

// Scratch (static device globals -- no allocation allowed)
__device__ __align__(256) float g_tmp[(size_t)NN * F];   // GEMM output (pre-norm messages)
__device__ __align__(256) float g_agg[(size_t)NN * F];   // aggregation buffer (next layer input)
__device__ __align__(256) float g_dis[NN];               // rsqrt(deg)
__device__ __align__(256) int   g_cnt[NN];               // in-degree (excl. self loop)
__device__ __align__(256) int   g_rowstart[NN];          // scan -> start; after place -> end
__device__ __align__(256) int   g_bsum[512];             // scan block sums
__device__ __align__(256) int   g_boff[512];             // scan block offsets
__device__ __align__(256) int2  g_epack[EE];             // per-edge (src, norm-bits), dst-sorted

// ---------------------------------------------------------------------------
// CSR build: count, scan(+dis), place (rowstart doubles as cursor)
// ---------------------------------------------------------------------------
__global__ void k_zero(int n) {
    int i = blockIdx.x * blockDim.x + threadIdx.x;
    if (i < n) g_cnt[i] = 0;
}

__global__ void k_count(const int* __restrict__ ei, int E) {
    int e = blockIdx.x * blockDim.x + threadIdx.x;
    if (e < E) atomicAdd(&g_cnt[ei[E + e]], 1);
}

__global__ void k_scan1(int n) {   // block-local exclusive scan + dis
    __shared__ int s[SCAN_B];
    int i = blockIdx.x * SCAN_B + threadIdx.x;
    int v = (i < n) ? g_cnt[i] : 0;
    s[threadIdx.x] = v;
    __syncthreads();
    for (int off = 1; off < SCAN_B; off <<= 1) {
        int t = (threadIdx.x >= off) ? s[threadIdx.x - off] : 0;
        __syncthreads();
        s[threadIdx.x] += t;
        __syncthreads();
    }
    if (i < n) {
        g_rowstart[i] = s[threadIdx.x] - v;   // exclusive within block
        g_dis[i] = rsqrtf((float)(v + 1));    // +1 self loop
    }
    if (threadIdx.x == SCAN_B - 1) g_bsum[blockIdx.x] = s[SCAN_B - 1];
}

__global__ void k_scan2(int nb) {  // single block, 512 threads
    __shared__ int s[512];
    int v = (threadIdx.x < nb) ? g_bsum[threadIdx.x] : 0;
    s[threadIdx.x] = v;
    __syncthreads();
    for (int off = 1; off < 512; off <<= 1) {
        int t = (threadIdx.x >= off) ? s[threadIdx.x - off] : 0;
        __syncthreads();
        s[threadIdx.x] += t;
        __syncthreads();
    }
    if (threadIdx.x < nb) g_boff[threadIdx.x] = s[threadIdx.x] - v;  // exclusive
}

__global__ void k_scan3(int n) {
    int i = blockIdx.x * SCAN_B + threadIdx.x;
    if (i < n) g_rowstart[i] += g_boff[blockIdx.x];
}

// Place edges; atomicAdd on rowstart acts as cursor. After this kernel,
// rowstart[i] == row END; start is recovered as end - cnt.
__global__ void k_place(const int* __restrict__ ei, int E) {
    int e = blockIdx.x * blockDim.x + threadIdx.x;
    if (e < E) {
        int src = ei[e];
        int dst = ei[E + e];
        int pos = atomicAdd(&g_rowstart[dst], 1);
        float norm = g_dis[src] * g_dis[dst];
        g_epack[pos] = make_int2(src, __float_as_int(norm));
    }
}

// ---------------------------------------------------------------------------
// GEMM: tmp = (relu?)(hin) @ W   [N,64]x[64,64]
// Register-tiled: 64-row tile per 256-thread block, 4x4 outputs per thread.
// Also writes agg = b + tmp * dis^2  (bias + self-loop message, fused).
// ---------------------------------------------------------------------------
__global__ void __launch_bounds__(256) k_gemm(
        const float* __restrict__ hin_ext,
        const float* __restrict__ W,
        const float* __restrict__ b,
        int n, int use_agg_in) {
    __shared__ float Ws[F * F];        // W[k][c], row-major (as given)
    __shared__ float hs[F][F + 1];     // h[r][k], padded

    int tid = threadIdx.x;             // 0..255
    int tx  = tid & 15;                // col group 0..15
    int ty  = tid >> 4;                // row group 0..15
    int row0 = blockIdx.x * F;

    for (int i = tid; i < F * F; i += 256) Ws[i] = W[i];

    for (int i = tid; i < F * F; i += 256) {
        int r = i >> 6, f = i & 63;
        int row = row0 + r;
        float v = 0.0f;
        if (row < n) {
            v = use_agg_in ? fmaxf(g_agg[(size_t)row * F + f], 0.0f)
                           : hin_ext[(size_t)row * F + f];
        }
        hs[r][f] = v;
    }
    __syncthreads();

    int c0 = tx * 4;
    int r0 = ty * 4;

    float acc[4][4];
#pragma unroll
    for (int i = 0; i < 4; i++)
#pragma unroll
        for (int j = 0; j < 4; j++) acc[i][j] = 0.0f;

#pragma unroll 8
    for (int k = 0; k < F; k++) {
        float4 wv = *reinterpret_cast<const float4*>(&Ws[k * F + c0]);
        float h0 = hs[r0 + 0][k];
        float h1 = hs[r0 + 1][k];
        float h2 = hs[r0 + 2][k];
        float h3 = hs[r0 + 3][k];
        acc[0][0] = fmaf(h0, wv.x, acc[0][0]); acc[0][1] = fmaf(h0, wv.y, acc[0][1]);
        acc[0][2] = fmaf(h0, wv.z, acc[0][2]); acc[0][3] = fmaf(h0, wv.w, acc[0][3]);
        acc[1][0] = fmaf(h1, wv.x, acc[1][0]); acc[1][1] = fmaf(h1, wv.y, acc[1][1]);
        acc[1][2] = fmaf(h1, wv.z, acc[1][2]); acc[1][3] = fmaf(h1, wv.w, acc[1][3]);
        acc[2][0] = fmaf(h2, wv.x, acc[2][0]); acc[2][1] = fmaf(h2, wv.y, acc[2][1]);
        acc[2][2] = fmaf(h2, wv.z, acc[2][2]); acc[2][3] = fmaf(h2, wv.w, acc[2][3]);
        acc[3][0] = fmaf(h3, wv.x, acc[3][0]); acc[3][1] = fmaf(h3, wv.y, acc[3][1]);
        acc[3][2] = fmaf(h3, wv.z, acc[3][2]); acc[3][3] = fmaf(h3, wv.w, acc[3][3]);
    }

    float4 bv = *reinterpret_cast<const float4*>(b + c0);

#pragma unroll
    for (int i = 0; i < 4; i++) {
        int row = row0 + r0 + i;
        if (row < n) {
            float4 t = make_float4(acc[i][0], acc[i][1], acc[i][2], acc[i][3]);
            *reinterpret_cast<float4*>(g_tmp + (size_t)row * F + c0) = t;
            float d = g_dis[row];
            float d2 = d * d;
            float4 a = make_float4(bv.x + t.x * d2, bv.y + t.y * d2,
                                   bv.z + t.z * d2, bv.w + t.w * d2);
            *reinterpret_cast<float4*>(g_agg + (size_t)row * F + c0) = a;
        }
    }
}

// ---------------------------------------------------------------------------
// Aggregation (CSR gather, NO atomics): for each node i,
//   agg[i] += sum_{e in row(i)} tmp[src(e)] * norm(e)
// 16 threads per node, one float4 slice each; 4 independent chains (MLP 4).
// ---------------------------------------------------------------------------
__global__ void k_agg(int n) {
    int tx   = threadIdx.x & 15;         // float4 slice 0..15
    int node = blockIdx.x * 16 + (threadIdx.x >> 4);
    if (node >= n) return;

    int end   = g_rowstart[node];        // post-place: end
    int start = end - g_cnt[node];

    float4 a0 = make_float4(0.f, 0.f, 0.f, 0.f);
    float4 a1 = make_float4(0.f, 0.f, 0.f, 0.f);
    float4 a2 = make_float4(0.f, 0.f, 0.f, 0.f);
    float4 a3 = make_float4(0.f, 0.f, 0.f, 0.f);

    int k = start;
    for (; k + 3 < end; k += 4) {
        int2 p0 = g_epack[k + 0];
        int2 p1 = g_epack[k + 1];
        int2 p2 = g_epack[k + 2];
        int2 p3 = g_epack[k + 3];
        const float4 v0 = *reinterpret_cast<const float4*>(g_tmp + (size_t)p0.x * F + tx * 4);
        const float4 v1 = *reinterpret_cast<const float4*>(g_tmp + (size_t)p1.x * F + tx * 4);
        const float4 v2 = *reinterpret_cast<const float4*>(g_tmp + (size_t)p2.x * F + tx * 4);
        const float4 v3 = *reinterpret_cast<const float4*>(g_tmp + (size_t)p3.x * F + tx * 4);
        float n0 = __int_as_float(p0.y), n1 = __int_as_float(p1.y);
        float n2 = __int_as_float(p2.y), n3 = __int_as_float(p3.y);
        a0.x = fmaf(v0.x, n0, a0.x); a0.y = fmaf(v0.y, n0, a0.y);
        a0.z = fmaf(v0.z, n0, a0.z); a0.w = fmaf(v0.w, n0, a0.w);
        a1.x = fmaf(v1.x, n1, a1.x); a1.y = fmaf(v1.y, n1, a1.y);
        a1.z = fmaf(v1.z, n1, a1.z); a1.w = fmaf(v1.w, n1, a1.w);
        a2.x = fmaf(v2.x, n2, a2.x); a2.y = fmaf(v2.y, n2, a2.y);
        a2.z = fmaf(v2.z, n2, a2.z); a2.w = fmaf(v2.w, n2, a2.w);
        a3.x = fmaf(v3.x, n3, a3.x); a3.y = fmaf(v3.y, n3, a3.y);
        a3.z = fmaf(v3.z, n3, a3.z); a3.w = fmaf(v3.w, n3, a3.w);
    }
    for (; k < end; k++) {
        int2 p0 = g_epack[k];
        float n0 = __int_as_float(p0.y);
        const float4 v0 = *reinterpret_cast<const float4*>(g_tmp + (size_t)p0.x * F + tx * 4);
        a0.x = fmaf(v0.x, n0, a0.x); a0.y = fmaf(v0.y, n0, a0.y);
        a0.z = fmaf(v0.z, n0, a0.z); a0.w = fmaf(v0.w, n0, a0.w);
    }

    float* pa = g_agg + (size_t)node * F + tx * 4;
    float4 cur = *reinterpret_cast<float4*>(pa);
    cur.x += (a0.x + a1.x) + (a2.x + a3.x);
    cur.y += (a0.y + a1.y) + (a2.y + a3.y);
    cur.z += (a0.z + a1.z) + (a2.z + a3.z);
    cur.w += (a0.w + a1.w) + (a2.w + a3.w);
    *reinterpret_cast<float4*>(pa) = cur;
}

// ---------------------------------------------------------------------------
// Final linear: out = relu(agg) @ Wl + bl   [N,64]x[64,8]
// ---------------------------------------------------------------------------
__global__ void k_final(const float* __restrict__ Wl,
                        const float* __restrict__ bl,
                        float* __restrict__ out, int n) {
    __shared__ float Wls[F * OUTF];
    __shared__ float hs[32][F + 1];

    int tx  = threadIdx.x;  // 0..7
    int ty  = threadIdx.y;  // 0..31
    int tid = ty * OUTF + tx;

    for (int i = tid; i < F * OUTF; i += 256) Wls[i] = Wl[i];

    int row0 = blockIdx.x * 32;
    for (int i = tid; i < 32 * F; i += 256) {
        int r = row0 + i / F;
        hs[i / F][i % F] = (r < n) ? fmaxf(g_agg[(size_t)r * F + (i % F)], 0.0f) : 0.0f;
    }
    __syncthreads();

    int row = row0 + ty;
    if (row < n) {
        float acc = bl[tx];
#pragma unroll
        for (int k = 0; k < F; k++)
            acc = fmaf(hs[ty][k], Wls[k * OUTF + tx], acc);
        out[(size_t)row * OUTF + tx] = acc;
    }
}

// ---------------------------------------------------------------------------
// Launch
// ---------------------------------------------------------------------------
extern "C" void kernel_launch(void* const* d_in, const int* in_sizes, int n_in,
                              void* d_out, int out_size) {
    const float* x  = (const float*)d_in[0];
    const int*   ei = (const int*)d_in[1];     // int32 edge_index [2, E]
    const float* W1 = (const float*)d_in[2];
    const float* b1 = (const float*)d_in[3];
    const float* W2 = (const float*)d_in[4];
    const float* b2 = (const float*)d_in[5];
    const float* W3 = (const float*)d_in[6];
    const float* b3 = (const float*)d_in[7];
    const float* Wl = (const float*)d_in[8];
    const float* bl = (const float*)d_in[9];
    float* out = (float*)d_out;

    int n = in_sizes[0] / F;        // 100000
    int E = in_sizes[1] / 2;        // 1600000

    unsigned ngrid = (unsigned)((n + 255) / 256);
    unsigned egrid = (unsigned)((E + 255) / 256);
    unsigned sgrid = (unsigned)((n + SCAN_B - 1) / SCAN_B);

    // --- CSR build (once per call, reused by 3 aggregations) ---
    k_zero<<<ngrid, 256>>>(n);
    k_count<<<egrid, 256>>>(ei, E);
    k_scan1<<<sgrid, SCAN_B>>>(n);
    k_scan2<<<1, 512>>>((int)sgrid);
    k_scan3<<<sgrid, SCAN_B>>>(n);
    k_place<<<egrid, 256>>>(ei, E);

    unsigned gemm_grid = (unsigned)((n + F - 1) / F);
    unsigned agg_grid  = (unsigned)((n + 15) / 16);

    // --- layer 1 ---
    k_gemm<<<gemm_grid, 256>>>(x, W1, b1, n, 0);
    k_agg<<<agg_grid, 256>>>(n);
    // --- layer 2 (relu fused into gemm read) ---
    k_gemm<<<gemm_grid, 256>>>(nullptr, W2, b2, n, 1);
    k_agg<<<agg_grid, 256>>>(n);
    // --- layer 3 ---
    k_gemm<<<gemm_grid, 256>>>(nullptr, W3, b3, n, 1);
    k_agg<<<agg_grid, 256>>>(n);

    // --- final linear (relu fused) ---
    dim3 fin_block(OUTF, 32);
    k_final<<<(n + 31) / 32, fin_block>>>(Wl, bl, out, n);
}

// round 8
// speedup vs baseline: 3.4950x; 1.0768x over previous
#include <cuda_runtime.h>
#include <cstdint>

// Problem constants (GCNN3L: N=100000 nodes, F=64 features, 8 outputs)
#define NN 100000
#define EE 1600000
#define F  64
#define OUTF 8

#define SCAN_B 256

// Scratch (static device globals -- no allocation allowed)
__device__ __align__(256) float g_tmpA[(size_t)NN * F];  // scaled GEMM output, buffer A
__device__ __align__(256) float g_tmpB[(size_t)NN * F];  // scaled GEMM output, buffer B
__device__ __align__(256) float g_dis[NN];               // rsqrt(deg)
__device__ __align__(256) int   g_cnt[NN];               // in-degree (excl. self loop)
__device__ __align__(256) int   g_rowstart[NN];          // scan -> start; after place -> end
__device__ __align__(256) int   g_bsum[512];             // scan block sums
__device__ __align__(256) int   g_boff[512];             // scan block offsets
__device__ __align__(256) int   g_esrc[EE];              // per-edge src, dst-sorted

// ---------------------------------------------------------------------------
// CSR build: count, scan(+dis), place (rowstart doubles as cursor)
// ---------------------------------------------------------------------------
__global__ void k_zero(int n) {
    int i = blockIdx.x * blockDim.x + threadIdx.x;
    if (i < n) g_cnt[i] = 0;
}

__global__ void k_count(const int* __restrict__ ei, int E) {
    int e = blockIdx.x * blockDim.x + threadIdx.x;
    if (e < E) atomicAdd(&g_cnt[ei[E + e]], 1);
}

__global__ void k_scan1(int n) {   // block-local exclusive scan + dis
    __shared__ int s[SCAN_B];
    int i = blockIdx.x * SCAN_B + threadIdx.x;
    int v = (i < n) ? g_cnt[i] : 0;
    s[threadIdx.x] = v;
    __syncthreads();
    for (int off = 1; off < SCAN_B; off <<= 1) {
        int t = (threadIdx.x >= off) ? s[threadIdx.x - off] : 0;
        __syncthreads();
        s[threadIdx.x] += t;
        __syncthreads();
    }
    if (i < n) {
        g_rowstart[i] = s[threadIdx.x] - v;   // exclusive within block
        g_dis[i] = rsqrtf((float)(v + 1));    // +1 self loop
    }
    if (threadIdx.x == SCAN_B - 1) g_bsum[blockIdx.x] = s[SCAN_B - 1];
}

__global__ void k_scan2(int nb) {  // single block, 512 threads
    __shared__ int s[512];
    int v = (threadIdx.x < nb) ? g_bsum[threadIdx.x] : 0;
    s[threadIdx.x] = v;
    __syncthreads();
    for (int off = 1; off < 512; off <<= 1) {
        int t = (threadIdx.x >= off) ? s[threadIdx.x - off] : 0;
        __syncthreads();
        s[threadIdx.x] += t;
        __syncthreads();
    }
    if (threadIdx.x < nb) g_boff[threadIdx.x] = s[threadIdx.x] - v;  // exclusive
}

__global__ void k_scan3(int n) {
    int i = blockIdx.x * SCAN_B + threadIdx.x;
    if (i < n) g_rowstart[i] += g_boff[blockIdx.x];
}

// Place edges; atomicAdd on rowstart acts as cursor. After this kernel,
// rowstart[i] == row END; start is recovered as end - cnt.
__global__ void k_place(const int* __restrict__ ei, int E) {
    int e = blockIdx.x * blockDim.x + threadIdx.x;
    if (e < E) {
        int src = ei[e];
        int dst = ei[E + e];
        int pos = atomicAdd(&g_rowstart[dst], 1);
        g_esrc[pos] = src;
    }
}

// ---------------------------------------------------------------------------
// Layer-1 GEMM: tmpA = (x @ W1) * dis   (scaled output; no bias here)
// Register-tiled: 64-row tile per 256-thread block, 4x4 outputs per thread.
// ---------------------------------------------------------------------------
__global__ void __launch_bounds__(256) k_gemm1(
        const float* __restrict__ x,
        const float* __restrict__ W,
        int n) {
    __shared__ float Ws[F * F];
    __shared__ float hs[F][F + 1];

    int tid = threadIdx.x;
    int tx  = tid & 15;
    int ty  = tid >> 4;
    int row0 = blockIdx.x * F;

    for (int i = tid; i < F * F; i += 256) Ws[i] = W[i];
    for (int i = tid; i < F * F; i += 256) {
        int r = i >> 6, f = i & 63;
        int row = row0 + r;
        hs[r][f] = (row < n) ? x[(size_t)row * F + f] : 0.0f;
    }
    __syncthreads();

    int c0 = tx * 4, r0 = ty * 4;
    float acc[4][4];
#pragma unroll
    for (int i = 0; i < 4; i++)
#pragma unroll
        for (int j = 0; j < 4; j++) acc[i][j] = 0.0f;

#pragma unroll 8
    for (int k = 0; k < F; k++) {
        float4 wv = *reinterpret_cast<const float4*>(&Ws[k * F + c0]);
        float h0 = hs[r0 + 0][k], h1 = hs[r0 + 1][k];
        float h2 = hs[r0 + 2][k], h3 = hs[r0 + 3][k];
        acc[0][0] = fmaf(h0, wv.x, acc[0][0]); acc[0][1] = fmaf(h0, wv.y, acc[0][1]);
        acc[0][2] = fmaf(h0, wv.z, acc[0][2]); acc[0][3] = fmaf(h0, wv.w, acc[0][3]);
        acc[1][0] = fmaf(h1, wv.x, acc[1][0]); acc[1][1] = fmaf(h1, wv.y, acc[1][1]);
        acc[1][2] = fmaf(h1, wv.z, acc[1][2]); acc[1][3] = fmaf(h1, wv.w, acc[1][3]);
        acc[2][0] = fmaf(h2, wv.x, acc[2][0]); acc[2][1] = fmaf(h2, wv.y, acc[2][1]);
        acc[2][2] = fmaf(h2, wv.z, acc[2][2]); acc[2][3] = fmaf(h2, wv.w, acc[2][3]);
        acc[3][0] = fmaf(h3, wv.x, acc[3][0]); acc[3][1] = fmaf(h3, wv.y, acc[3][1]);
        acc[3][2] = fmaf(h3, wv.z, acc[3][2]); acc[3][3] = fmaf(h3, wv.w, acc[3][3]);
    }

#pragma unroll
    for (int i = 0; i < 4; i++) {
        int row = row0 + r0 + i;
        if (row < n) {
            float d = g_dis[row];
            float4 t = make_float4(acc[i][0] * d, acc[i][1] * d,
                                   acc[i][2] * d, acc[i][3] * d);
            *reinterpret_cast<float4*>(g_tmpA + (size_t)row * F + c0) = t;
        }
    }
}

// ---------------------------------------------------------------------------
// Fused layer: for a 64-row tile,
//   agg phase:  h[r] = relu(b + dis[r] * (tin[r] + sum_{src in row(r)} tin[src]))
//   gemm phase: tout[r] = (h @ W) * dis[r]
// tin/tout are the double-buffered scaled-tmp arrays.
// ---------------------------------------------------------------------------
__global__ void __launch_bounds__(256) k_fused(
        const float* __restrict__ tin,
        float* __restrict__ tout,
        const float* __restrict__ b,   // bias of the AGG layer
        const float* __restrict__ W,   // weights of the NEXT gemm
        int n) {
    __shared__ float Ws[F * F];
    __shared__ float hs[F][F + 1];

    int tid = threadIdx.x;
    int tx  = tid & 15;                 // float4 slice / col group
    int grp = tid >> 4;                 // node group 0..15
    int row0 = blockIdx.x * F;
    int c0 = tx * 4;

    // Load W first (its latency overlaps the gather phase below)
    for (int i = tid; i < F * F; i += 256) Ws[i] = W[i];

    float4 bv = *reinterpret_cast<const float4*>(b + c0);

    // --- agg phase: 4 batches of 16 nodes, 16 threads per node ---
#pragma unroll
    for (int batch = 0; batch < 4; batch++) {
        int r = batch * 16 + grp;
        int node = row0 + r;
        if (node < n) {
            int end   = g_rowstart[node];        // post-place: end
            int start = end - g_cnt[node];

            // self term seeds the sum
            float4 a0 = *reinterpret_cast<const float4*>(tin + (size_t)node * F + c0);
            float4 a1 = make_float4(0.f, 0.f, 0.f, 0.f);
            float4 a2 = make_float4(0.f, 0.f, 0.f, 0.f);
            float4 a3 = make_float4(0.f, 0.f, 0.f, 0.f);

            int k = start;
            for (; k + 3 < end; k += 4) {
                int s0 = g_esrc[k + 0], s1 = g_esrc[k + 1];
                int s2 = g_esrc[k + 2], s3 = g_esrc[k + 3];
                const float4 v0 = *reinterpret_cast<const float4*>(tin + (size_t)s0 * F + c0);
                const float4 v1 = *reinterpret_cast<const float4*>(tin + (size_t)s1 * F + c0);
                const float4 v2 = *reinterpret_cast<const float4*>(tin + (size_t)s2 * F + c0);
                const float4 v3 = *reinterpret_cast<const float4*>(tin + (size_t)s3 * F + c0);
                a0.x += v0.x; a0.y += v0.y; a0.z += v0.z; a0.w += v0.w;
                a1.x += v1.x; a1.y += v1.y; a1.z += v1.z; a1.w += v1.w;
                a2.x += v2.x; a2.y += v2.y; a2.z += v2.z; a2.w += v2.w;
                a3.x += v3.x; a3.y += v3.y; a3.z += v3.z; a3.w += v3.w;
            }
            for (; k < end; k++) {
                int s0 = g_esrc[k];
                const float4 v0 = *reinterpret_cast<const float4*>(tin + (size_t)s0 * F + c0);
                a0.x += v0.x; a0.y += v0.y; a0.z += v0.z; a0.w += v0.w;
            }

            float d = g_dis[node];
            hs[r][c0 + 0] = fmaxf(fmaf(d, (a0.x + a1.x) + (a2.x + a3.x), bv.x), 0.0f);
            hs[r][c0 + 1] = fmaxf(fmaf(d, (a0.y + a1.y) + (a2.y + a3.y), bv.y), 0.0f);
            hs[r][c0 + 2] = fmaxf(fmaf(d, (a0.z + a1.z) + (a2.z + a3.z), bv.z), 0.0f);
            hs[r][c0 + 3] = fmaxf(fmaf(d, (a0.w + a1.w) + (a2.w + a3.w), bv.w), 0.0f);
        } else if (r < F) {
            hs[r][c0 + 0] = 0.0f; hs[r][c0 + 1] = 0.0f;
            hs[r][c0 + 2] = 0.0f; hs[r][c0 + 3] = 0.0f;
        }
    }
    __syncthreads();

    // --- gemm phase (identical tiling to k_gemm1) ---
    int r0 = grp * 4;
    float acc[4][4];
#pragma unroll
    for (int i = 0; i < 4; i++)
#pragma unroll
        for (int j = 0; j < 4; j++) acc[i][j] = 0.0f;

#pragma unroll 8
    for (int k = 0; k < F; k++) {
        float4 wv = *reinterpret_cast<const float4*>(&Ws[k * F + c0]);
        float h0 = hs[r0 + 0][k], h1 = hs[r0 + 1][k];
        float h2 = hs[r0 + 2][k], h3 = hs[r0 + 3][k];
        acc[0][0] = fmaf(h0, wv.x, acc[0][0]); acc[0][1] = fmaf(h0, wv.y, acc[0][1]);
        acc[0][2] = fmaf(h0, wv.z, acc[0][2]); acc[0][3] = fmaf(h0, wv.w, acc[0][3]);
        acc[1][0] = fmaf(h1, wv.x, acc[1][0]); acc[1][1] = fmaf(h1, wv.y, acc[1][1]);
        acc[1][2] = fmaf(h1, wv.z, acc[1][2]); acc[1][3] = fmaf(h1, wv.w, acc[1][3]);
        acc[2][0] = fmaf(h2, wv.x, acc[2][0]); acc[2][1] = fmaf(h2, wv.y, acc[2][1]);
        acc[2][2] = fmaf(h2, wv.z, acc[2][2]); acc[2][3] = fmaf(h2, wv.w, acc[2][3]);
        acc[3][0] = fmaf(h3, wv.x, acc[3][0]); acc[3][1] = fmaf(h3, wv.y, acc[3][1]);
        acc[3][2] = fmaf(h3, wv.z, acc[3][2]); acc[3][3] = fmaf(h3, wv.w, acc[3][3]);
    }

#pragma unroll
    for (int i = 0; i < 4; i++) {
        int row = row0 + r0 + i;
        if (row < n) {
            float d = g_dis[row];
            float4 t = make_float4(acc[i][0] * d, acc[i][1] * d,
                                   acc[i][2] * d, acc[i][3] * d);
            *reinterpret_cast<float4*>(tout + (size_t)row * F + c0) = t;
        }
    }
}

// ---------------------------------------------------------------------------
// Fused final: agg phase (layer-3 bias b3) then out = h @ Wl + bl  [64x8]
// ---------------------------------------------------------------------------
__global__ void __launch_bounds__(256) k_fused_final(
        const float* __restrict__ tin,
        const float* __restrict__ b,    // b3
        const float* __restrict__ Wl,   // [64,8]
        const float* __restrict__ bl,   // [8]
        float* __restrict__ out,
        int n) {
    __shared__ float Wls[F * OUTF];
    __shared__ float hs[F][F + 1];

    int tid = threadIdx.x;
    int tx  = tid & 15;
    int grp = tid >> 4;
    int row0 = blockIdx.x * F;
    int c0 = tx * 4;

    for (int i = tid; i < F * OUTF; i += 256) Wls[i] = Wl[i];

    float4 bv = *reinterpret_cast<const float4*>(b + c0);

#pragma unroll
    for (int batch = 0; batch < 4; batch++) {
        int r = batch * 16 + grp;
        int node = row0 + r;
        if (node < n) {
            int end   = g_rowstart[node];
            int start = end - g_cnt[node];

            float4 a0 = *reinterpret_cast<const float4*>(tin + (size_t)node * F + c0);
            float4 a1 = make_float4(0.f, 0.f, 0.f, 0.f);
            float4 a2 = make_float4(0.f, 0.f, 0.f, 0.f);
            float4 a3 = make_float4(0.f, 0.f, 0.f, 0.f);

            int k = start;
            for (; k + 3 < end; k += 4) {
                int s0 = g_esrc[k + 0], s1 = g_esrc[k + 1];
                int s2 = g_esrc[k + 2], s3 = g_esrc[k + 3];
                const float4 v0 = *reinterpret_cast<const float4*>(tin + (size_t)s0 * F + c0);
                const float4 v1 = *reinterpret_cast<const float4*>(tin + (size_t)s1 * F + c0);
                const float4 v2 = *reinterpret_cast<const float4*>(tin + (size_t)s2 * F + c0);
                const float4 v3 = *reinterpret_cast<const float4*>(tin + (size_t)s3 * F + c0);
                a0.x += v0.x; a0.y += v0.y; a0.z += v0.z; a0.w += v0.w;
                a1.x += v1.x; a1.y += v1.y; a1.z += v1.z; a1.w += v1.w;
                a2.x += v2.x; a2.y += v2.y; a2.z += v2.z; a2.w += v2.w;
                a3.x += v3.x; a3.y += v3.y; a3.z += v3.z; a3.w += v3.w;
            }
            for (; k < end; k++) {
                int s0 = g_esrc[k];
                const float4 v0 = *reinterpret_cast<const float4*>(tin + (size_t)s0 * F + c0);
                a0.x += v0.x; a0.y += v0.y; a0.z += v0.z; a0.w += v0.w;
            }

            float d = g_dis[node];
            hs[r][c0 + 0] = fmaxf(fmaf(d, (a0.x + a1.x) + (a2.x + a3.x), bv.x), 0.0f);
            hs[r][c0 + 1] = fmaxf(fmaf(d, (a0.y + a1.y) + (a2.y + a3.y), bv.y), 0.0f);
            hs[r][c0 + 2] = fmaxf(fmaf(d, (a0.z + a1.z) + (a2.z + a3.z), bv.z), 0.0f);
            hs[r][c0 + 3] = fmaxf(fmaf(d, (a0.w + a1.w) + (a2.w + a3.w), bv.w), 0.0f);
        } else if (r < F) {
            hs[r][c0 + 0] = 0.0f; hs[r][c0 + 1] = 0.0f;
            hs[r][c0 + 2] = 0.0f; hs[r][c0 + 3] = 0.0f;
        }
    }
    __syncthreads();

    // --- final 64x8 gemm: each thread computes 2 outputs ---
    int r = tid >> 2;                  // 0..63
    int c = (tid & 3) * 2;             // 0,2,4,6
    int row = row0 + r;
    if (row < n) {
        float acc0 = bl[c], acc1 = bl[c + 1];
#pragma unroll
        for (int k = 0; k < F; k++) {
            float h = hs[r][k];
            acc0 = fmaf(h, Wls[k * OUTF + c], acc0);
            acc1 = fmaf(h, Wls[k * OUTF + c + 1], acc1);
        }
        float2 o = make_float2(acc0, acc1);
        *reinterpret_cast<float2*>(out + (size_t)row * OUTF + c) = o;
    }
}

// ---------------------------------------------------------------------------
// Launch
// ---------------------------------------------------------------------------
extern "C" void kernel_launch(void* const* d_in, const int* in_sizes, int n_in,
                              void* d_out, int out_size) {
    const float* x  = (const float*)d_in[0];
    const int*   ei = (const int*)d_in[1];     // int32 edge_index [2, E]
    const float* W1 = (const float*)d_in[2];
    const float* b1 = (const float*)d_in[3];
    const float* W2 = (const float*)d_in[4];
    const float* b2 = (const float*)d_in[5];
    const float* W3 = (const float*)d_in[6];
    const float* b3 = (const float*)d_in[7];
    const float* Wl = (const float*)d_in[8];
    const float* bl = (const float*)d_in[9];
    float* out = (float*)d_out;

    int n = in_sizes[0] / F;        // 100000
    int E = in_sizes[1] / 2;        // 1600000

    unsigned ngrid = (unsigned)((n + 255) / 256);
    unsigned egrid = (unsigned)((E + 255) / 256);
    unsigned sgrid = (unsigned)((n + SCAN_B - 1) / SCAN_B);

    // --- CSR build (reused by all 3 aggregations) ---
    k_zero<<<ngrid, 256>>>(n);
    k_count<<<egrid, 256>>>(ei, E);
    k_scan1<<<sgrid, SCAN_B>>>(n);
    k_scan2<<<1, 512>>>((int)sgrid);
    k_scan3<<<sgrid, SCAN_B>>>(n);
    k_place<<<egrid, 256>>>(ei, E);

    unsigned tile_grid = (unsigned)((n + F - 1) / F);

    float *tA = nullptr, *tB = nullptr;
    cudaGetSymbolAddress((void**)&tA, g_tmpA);
    cudaGetSymbolAddress((void**)&tB, g_tmpB);

    // layer 1 gemm -> A; fused(agg1 + gemm2) A->B; fused(agg2 + gemm3) B->A;
    // fused final(agg3 + linear) A->out
    k_gemm1<<<tile_grid, 256>>>(x, W1, n);
    k_fused<<<tile_grid, 256>>>(tA, tB, b1, W2, n);
    k_fused<<<tile_grid, 256>>>(tB, tA, b2, W3, n);
    k_fused_final<<<tile_grid, 256>>>(tA, b3, Wl, bl, out, n);
}